// round 6
// baseline (speedup 1.0000x reference)
#include <cuda_runtime.h>
#include <cuda_bf16.h>
#include <math.h>
#include <stdint.h>

#define Bz 512
#define Sz 100
#define Ez 256
#define Hz 256
#define G4 1024
#define C_EXPLORE 10.0f
#define PARTITIONABLE 1

// ---------------- device state ----------------
__device__ float g_h0[Bz * Hz];
__device__ float g_h1[Bz * Hz];
__device__ float g_c[Bz * Hz];
__device__ float g_enc[(size_t)Bz * Sz * Hz];
__device__ float g_refg[(size_t)Bz * Sz * Hz];
__device__ float g_refp[(size_t)Bz * Sz * Hz];
__device__ float g_Penc[2 * G4];
__device__ float g_Pdec[2 * G4];
__device__ float g_startproj[G4];
__device__ int g_idx[Bz];
__device__ unsigned char g_mask[Bz * Sz];

// ---------------- XLA/Eigen rational tanh (branchless, matches reference lowering) ----------------
__device__ __forceinline__ float xtanh(float x) {
    const float c = 7.90531110763549805f;
    float cx = fminf(fmaxf(x, -c), c);
    float r = cx * cx;
    float p = -2.76076847742355e-16f;
    p = fmaf(p, r, 2.00018790482477e-13f);
    p = fmaf(p, r, -8.60467152213735e-11f);
    p = fmaf(p, r, 5.12229709037114e-08f);
    p = fmaf(p, r, 1.48572235717979e-05f);
    p = fmaf(p, r, 6.37261928875436e-04f);
    p = fmaf(p, r, 4.89352455891786e-03f);
    float num = cx * p;
    float q = 1.19825839466702e-06f;
    q = fmaf(q, r, 1.18534705686654e-04f);
    q = fmaf(q, r, 2.26843463243900e-03f);
    q = fmaf(q, r, 4.89352518554385e-03f);
    return num / q;
}

__device__ __forceinline__ float xsig(float x) {
    return 0.5f + 0.5f * xtanh(0.5f * x);
}

// ---------------- threefry2x32 ----------------
__device__ __forceinline__ unsigned rotl32(unsigned v, int r) {
    return (v << r) | (v >> (32 - r));
}
__device__ __forceinline__ void tf2x32(unsigned k0, unsigned k1,
                                       unsigned x0, unsigned x1,
                                       unsigned& o0, unsigned& o1) {
    unsigned ks2 = 0x1BD11BDAu ^ k0 ^ k1;
    x0 += k0; x1 += k1;
#define TF_G(a,b,c,d) \
    x0 += x1; x1 = rotl32(x1,a); x1 ^= x0; \
    x0 += x1; x1 = rotl32(x1,b); x1 ^= x0; \
    x0 += x1; x1 = rotl32(x1,c); x1 ^= x0; \
    x0 += x1; x1 = rotl32(x1,d); x1 ^= x0;
    TF_G(13,15,26,6);  x0 += k1;  x1 += ks2 + 1u;
    TF_G(17,29,16,24); x0 += ks2; x1 += k0 + 2u;
    TF_G(13,15,26,6);  x0 += k0;  x1 += k1 + 3u;
    TF_G(17,29,16,24); x0 += k1;  x1 += ks2 + 4u;
    TF_G(13,15,26,6);  x0 += ks2; x1 += k0 + 5u;
#undef TF_G
    o0 = x0; o1 = x1;
}

// ---------------- setup ----------------
__global__ void k_init() {
    int i = blockIdx.x * blockDim.x + threadIdx.x;
    if (i < Bz * Hz) { g_h0[i] = 0.f; g_c[i] = 0.f; }
    if (i < Bz * Sz) g_mask[i] = 0;
    if (i < Bz) g_idx[i] = 0;
}

__global__ void k_prep(const float* __restrict__ emb,
                       const float* __restrict__ eWih,
                       const float* __restrict__ dWih,
                       const float* __restrict__ start) {
    int j = blockIdx.x * 256 + threadIdx.x;
    if (j >= G4) return;
    float pe0 = 0.f, pe1 = 0.f, pd0 = 0.f, pd1 = 0.f, sp = 0.f;
    for (int e = 0; e < Ez; e++) {
        float we = eWih[j * Ez + e], wd = dWih[j * Ez + e];
        pe0 = fmaf(emb[e], we, pe0);
        pe1 = fmaf(emb[Ez + e], we, pe1);
        pd0 = fmaf(emb[e], wd, pd0);
        pd1 = fmaf(emb[Ez + e], wd, pd1);
        sp  = fmaf(start[e], wd, sp);
    }
    g_Penc[j] = pe0; g_Penc[G4 + j] = pe1;
    g_Pdec[j] = pd0; g_Pdec[G4 + j] = pd1;
    g_startproj[j] = sp;
}

// ---------------- fused gates GEMM + LSTM cell, double-buffered ----------------
// grid 128 blocks x 256 thr: block = 32 b-rows x 32 j-cols x 4 gates
__global__ void __launch_bounds__(256) k_lstm_step(const float* __restrict__ rh,
                                                   float* __restrict__ wh,
                                                   const float* __restrict__ W,
                                                   const float* __restrict__ bih,
                                                   const float* __restrict__ bhh,
                                                   const float* __restrict__ inp,
                                                   int t, int is_dec) {
    __shared__ float sA[2][32 * 36];       // [k][b], stride 36 (144B, 16B-aligned rows)
    __shared__ float sW[2][4 * 32 * 33];   // [g][k][j], stride 33
    const int tid = threadIdx.x, bid = blockIdx.x;
    const int tx = tid & 31, ty = tid >> 5;
    const int bm = (bid >> 3) * 32, jn = (bid & 7) * 32;
    const int j = jn + tx;
    const int lrow = tid >> 3;          // 0..31
    const int lk = (tid & 7) << 2;      // 0,4,..,28

    const float* Ab  = rh + (size_t)(bm + lrow) * Hz + lk;
    const float* Wb0 = W + (size_t)(jn + lrow) * Hz + lk;
    const float* Wb1 = Wb0 + (size_t)256 * Hz;
    const float* Wb2 = Wb0 + (size_t)512 * Hz;
    const float* Wb3 = Wb0 + (size_t)768 * Hz;

    float4 pa  = *(const float4*)Ab;
    float4 pw0 = *(const float4*)Wb0;
    float4 pw1 = *(const float4*)Wb1;
    float4 pw2 = *(const float4*)Wb2;
    float4 pw3 = *(const float4*)Wb3;

    float acc[4][4];
#pragma unroll
    for (int g = 0; g < 4; g++)
#pragma unroll
        for (int r = 0; r < 4; r++) acc[g][r] = 0.f;

    for (int k0 = 0; k0 < Hz; k0 += 32) {
        float* a_s = sA[(k0 >> 5) & 1];
        float* w_s = sW[(k0 >> 5) & 1];
        // store prefetched chunk
        a_s[(lk + 0) * 36 + lrow] = pa.x;
        a_s[(lk + 1) * 36 + lrow] = pa.y;
        a_s[(lk + 2) * 36 + lrow] = pa.z;
        a_s[(lk + 3) * 36 + lrow] = pa.w;
        {
            float* w0 = w_s;
            w0[(lk + 0) * 33 + lrow] = pw0.x; w0[(lk + 1) * 33 + lrow] = pw0.y;
            w0[(lk + 2) * 33 + lrow] = pw0.z; w0[(lk + 3) * 33 + lrow] = pw0.w;
            float* w1 = w_s + 1056;
            w1[(lk + 0) * 33 + lrow] = pw1.x; w1[(lk + 1) * 33 + lrow] = pw1.y;
            w1[(lk + 2) * 33 + lrow] = pw1.z; w1[(lk + 3) * 33 + lrow] = pw1.w;
            float* w2 = w_s + 2112;
            w2[(lk + 0) * 33 + lrow] = pw2.x; w2[(lk + 1) * 33 + lrow] = pw2.y;
            w2[(lk + 2) * 33 + lrow] = pw2.z; w2[(lk + 3) * 33 + lrow] = pw2.w;
            float* w3 = w_s + 3168;
            w3[(lk + 0) * 33 + lrow] = pw3.x; w3[(lk + 1) * 33 + lrow] = pw3.y;
            w3[(lk + 2) * 33 + lrow] = pw3.z; w3[(lk + 3) * 33 + lrow] = pw3.w;
        }
        __syncthreads();
        if (k0 + 32 < Hz) {
            pa  = *(const float4*)(Ab + k0 + 32);
            pw0 = *(const float4*)(Wb0 + k0 + 32);
            pw1 = *(const float4*)(Wb1 + k0 + 32);
            pw2 = *(const float4*)(Wb2 + k0 + 32);
            pw3 = *(const float4*)(Wb3 + k0 + 32);
        }
#pragma unroll 8
        for (int k = 0; k < 32; k++) {
            float4 a4 = *(const float4*)&a_s[k * 36 + (ty << 2)];  // broadcast
            float w0 = w_s[k * 33 + tx];
            float w1 = w_s[1056 + k * 33 + tx];
            float w2 = w_s[2112 + k * 33 + tx];
            float w3 = w_s[3168 + k * 33 + tx];
            acc[0][0] = fmaf(a4.x, w0, acc[0][0]); acc[0][1] = fmaf(a4.y, w0, acc[0][1]);
            acc[0][2] = fmaf(a4.z, w0, acc[0][2]); acc[0][3] = fmaf(a4.w, w0, acc[0][3]);
            acc[1][0] = fmaf(a4.x, w1, acc[1][0]); acc[1][1] = fmaf(a4.y, w1, acc[1][1]);
            acc[1][2] = fmaf(a4.z, w1, acc[1][2]); acc[1][3] = fmaf(a4.w, w1, acc[1][3]);
            acc[2][0] = fmaf(a4.x, w2, acc[2][0]); acc[2][1] = fmaf(a4.y, w2, acc[2][1]);
            acc[2][2] = fmaf(a4.z, w2, acc[2][2]); acc[2][3] = fmaf(a4.w, w2, acc[2][3]);
            acc[3][0] = fmaf(a4.x, w3, acc[3][0]); acc[3][1] = fmaf(a4.y, w3, acc[3][1]);
            acc[3][2] = fmaf(a4.z, w3, acc[3][2]); acc[3][3] = fmaf(a4.w, w3, acc[3][3]);
        }
    }

    const float* P = is_dec ? g_Pdec : g_Penc;
    float xb[4], pb0[4], pb1[4];
#pragma unroll
    for (int g = 0; g < 4; g++) {
        pb0[g] = P[(g << 8) + j];
        pb1[g] = P[G4 + (g << 8) + j];
        xb[g]  = bih[(g << 8) + j] + bhh[(g << 8) + j];
    }
#pragma unroll
    for (int r = 0; r < 4; r++) {
        int b = bm + (ty << 2) + r;
        float xg[4];
        if (is_dec && t == 0) {
#pragma unroll
            for (int g = 0; g < 4; g++) xg[g] = g_startproj[(g << 8) + j];
        } else {
            int s = is_dec ? g_idx[b] : t;
            float c0 = inp[(b * 2) * Sz + s];
            float c1 = inp[(b * 2 + 1) * Sz + s];
#pragma unroll
            for (int g = 0; g < 4; g++) xg[g] = fmaf(c0, pb0[g], c1 * pb1[g]);
        }
        float gi = acc[0][r] + xg[0] + xb[0];
        float gf = acc[1][r] + xg[1] + xb[1];
        float gc = acc[2][r] + xg[2] + xb[2];
        float go = acc[3][r] + xg[3] + xb[3];
        float cc = xsig(gf) * g_c[b * Hz + j] + xsig(gi) * xtanh(gc);
        g_c[b * Hz + j] = cc;
        float hh = xsig(go) * xtanh(cc);
        wh[b * Hz + j] = hh;
        if (!is_dec) g_enc[(size_t)(b * Sz + t) * Hz + j] = hh;
    }
}

// ---------------- ref projections (z=0: glimpse, z=1: pointer) ----------------
__global__ void __launch_bounds__(256) k_ref(const float* __restrict__ gWr,
                                             const float* __restrict__ gbr,
                                             const float* __restrict__ pWr,
                                             const float* __restrict__ pbr) {
    __shared__ float As[16][64];
    __shared__ float Ws[16][64];
    const float* A = g_enc;
    const float* W = blockIdx.z ? pWr : gWr;
    const float* bias = blockIdx.z ? pbr : gbr;
    float* C = blockIdx.z ? g_refp : g_refg;
    const int K = Hz, N = Hz;
    const int bm = blockIdx.y * 64;
    const int bn = blockIdx.x * 64;
    const int t = threadIdx.x;
    const int tx = t & 15, ty = t >> 4;
    const int lr = t >> 2, lc = (t & 3) << 2;
    float acc[4][4];
#pragma unroll
    for (int i = 0; i < 4; i++)
#pragma unroll
        for (int jj = 0; jj < 4; jj++) acc[i][jj] = 0.f;
    const float* Ab = A + (size_t)(bm + lr) * K + lc;
    const float* Wb = W + (size_t)(bn + lr) * K + lc;
    for (int k0 = 0; k0 < K; k0 += 16) {
        float4 av = *(const float4*)(Ab + k0);
        float4 wv = *(const float4*)(Wb + k0);
        As[lc + 0][lr] = av.x; As[lc + 1][lr] = av.y;
        As[lc + 2][lr] = av.z; As[lc + 3][lr] = av.w;
        Ws[lc + 0][lr] = wv.x; Ws[lc + 1][lr] = wv.y;
        Ws[lc + 2][lr] = wv.z; Ws[lc + 3][lr] = wv.w;
        __syncthreads();
#pragma unroll
        for (int k = 0; k < 16; k++) {
            float4 a4 = *(const float4*)&As[k][ty << 2];
            float4 w4 = *(const float4*)&Ws[k][tx << 2];
            float am[4] = {a4.x, a4.y, a4.z, a4.w};
            float wn[4] = {w4.x, w4.y, w4.z, w4.w};
#pragma unroll
            for (int i = 0; i < 4; i++)
#pragma unroll
                for (int jj = 0; jj < 4; jj++)
                    acc[i][jj] = fmaf(am[i], wn[jj], acc[i][jj]);
        }
        __syncthreads();
    }
#pragma unroll
    for (int i = 0; i < 4; i++) {
        int m = bm + (ty << 2) + i;
#pragma unroll
        for (int jj = 0; jj < 4; jj++) {
            int n = bn + (tx << 2) + jj;
            C[(size_t)m * N + n] = acc[i][jj] + bias[n];
        }
    }
}

// ---------------- fused decoder attention + sample: one block per b, 512 thr ----------------
__global__ void __launch_bounds__(512) k_dec_attn(const float* __restrict__ h,
                                                  const float* __restrict__ gWq,
                                                  const float* __restrict__ gbq,
                                                  const float* __restrict__ gV,
                                                  const float* __restrict__ pWq,
                                                  const float* __restrict__ pbq,
                                                  const float* __restrict__ pV,
                                                  float* __restrict__ out_probs,
                                                  float* __restrict__ out_idx,
                                                  int t) {
    __shared__ float s_h[Hz];
    __shared__ float s_qq[Hz];
    __shared__ float s_q[Hz];
    __shared__ float s_Vg[Hz];
    __shared__ float s_Vp[Hz];
    __shared__ float s_lg[128];
    __shared__ float s_w[128];
    __shared__ float s_red[512];
    __shared__ int s_ridx[512];
    __shared__ unsigned char s_m[104];

    const int b = blockIdx.x;
    const int tid = threadIdx.x;
    const int wd = tid >> 5, ln = tid & 31;

    if (t > 0 && tid == 0) g_mask[b * Sz + g_idx[b]] = 1;
    __syncthreads();
    if (tid < Sz) s_m[tid] = g_mask[b * Sz + tid];
    if (tid < Hz) {
        s_h[tid]  = h[b * Hz + tid];
        s_Vg[tid] = gV[tid];
        s_Vp[tid] = pV[tid];
    }
    __syncthreads();

    // qq = h @ gWq^T + gbq
    if (tid < Hz) {
        float a = 0.f;
        const float* wr = gWq + (size_t)tid * Hz;
#pragma unroll 8
        for (int k0 = 0; k0 < Hz; k0 += 4) {
            float4 wv = *(const float4*)&wr[k0];
            a = fmaf(s_h[k0], wv.x, a);
            a = fmaf(s_h[k0 + 1], wv.y, a);
            a = fmaf(s_h[k0 + 2], wv.z, a);
            a = fmaf(s_h[k0 + 3], wv.w, a);
        }
        s_qq[tid] = a + gbq[tid];
    }
    __syncthreads();
    // glimpse logits (16 warps over s)
    for (int s = wd; s < Sz; s += 16) {
        float a = 0.f;
        if (!s_m[s]) {
            const float4* rg4 = (const float4*)(g_refg + ((size_t)b * Sz + s) * Hz);
#pragma unroll
            for (int i = 0; i < 2; i++) {
                int c = i * 32 + ln;
                float4 rv = rg4[c];
                float4 qv = *(const float4*)&s_qq[c << 2];
                float4 vv = *(const float4*)&s_Vg[c << 2];
                a = fmaf(vv.x, xtanh(qv.x + rv.x), a);
                a = fmaf(vv.y, xtanh(qv.y + rv.y), a);
                a = fmaf(vv.z, xtanh(qv.z + rv.z), a);
                a = fmaf(vv.w, xtanh(qv.w + rv.w), a);
            }
        }
#pragma unroll
        for (int o = 16; o; o >>= 1) a += __shfl_xor_sync(0xffffffffu, a, o);
        if (!ln) s_lg[s] = s_m[s] ? -INFINITY : a;
    }
    __syncthreads();
    // softmax -> s_w
    {
        float v = (tid < Sz) ? s_lg[tid] : -INFINITY;
        s_red[tid] = v; __syncthreads();
#pragma unroll
        for (int o = 256; o; o >>= 1) { if (tid < o) s_red[tid] = fmaxf(s_red[tid], s_red[tid + o]); __syncthreads(); }
        float m = s_red[0]; __syncthreads();
        float e = (tid < Sz) ? expf(v - m) : 0.f;
        s_red[tid] = e; __syncthreads();
#pragma unroll
        for (int o = 256; o; o >>= 1) { if (tid < o) s_red[tid] += s_red[tid + o]; __syncthreads(); }
        float sm = s_red[0]; __syncthreads();
        if (tid < 128) s_w[tid] = (tid < Sz) ? e / sm : 0.f;
    }
    __syncthreads();
    // q = sum_s w[s] * enc[b,s,:]
    if (tid < Hz) {
        float a = 0.f;
        const float* eb = g_enc + (size_t)b * Sz * Hz + tid;
        for (int s = 0; s < Sz; s++) a = fmaf(s_w[s], eb[(size_t)s * Hz], a);
        s_q[tid] = a;
    }
    __syncthreads();
    // qq2 = q @ pWq^T + pbq
    if (tid < Hz) {
        float a = 0.f;
        const float* wr = pWq + (size_t)tid * Hz;
#pragma unroll 8
        for (int k0 = 0; k0 < Hz; k0 += 4) {
            float4 wv = *(const float4*)&wr[k0];
            a = fmaf(s_q[k0], wv.x, a);
            a = fmaf(s_q[k0 + 1], wv.y, a);
            a = fmaf(s_q[k0 + 2], wv.z, a);
            a = fmaf(s_q[k0 + 3], wv.w, a);
        }
        s_qq[tid] = a + pbq[tid];
    }
    __syncthreads();
    // pointer logits
    for (int s = wd; s < Sz; s += 16) {
        float a = 0.f;
        if (!s_m[s]) {
            const float4* rp4 = (const float4*)(g_refp + ((size_t)b * Sz + s) * Hz);
#pragma unroll
            for (int i = 0; i < 2; i++) {
                int c = i * 32 + ln;
                float4 rv = rp4[c];
                float4 qv = *(const float4*)&s_qq[c << 2];
                float4 vv = *(const float4*)&s_Vp[c << 2];
                a = fmaf(vv.x, xtanh(qv.x + rv.x), a);
                a = fmaf(vv.y, xtanh(qv.y + rv.y), a);
                a = fmaf(vv.z, xtanh(qv.z + rv.z), a);
                a = fmaf(vv.w, xtanh(qv.w + rv.w), a);
            }
        }
#pragma unroll
        for (int o = 16; o; o >>= 1) a += __shfl_xor_sync(0xffffffffu, a, o);
        if (!ln) s_lg[s] = s_m[s] ? -INFINITY : C_EXPLORE * xtanh(a);
    }
    __syncthreads();
    // softmax -> probs; gumbel argmax -> idx
    {
        float v = (tid < Sz) ? s_lg[tid] : -INFINITY;
        s_red[tid] = v; __syncthreads();
#pragma unroll
        for (int o = 256; o; o >>= 1) { if (tid < o) s_red[tid] = fmaxf(s_red[tid], s_red[tid + o]); __syncthreads(); }
        float m = s_red[0]; __syncthreads();
        float e = (tid < Sz) ? expf(v - m) : 0.f;
        s_red[tid] = e; __syncthreads();
#pragma unroll
        for (int o = 256; o; o >>= 1) { if (tid < o) s_red[tid] += s_red[tid + o]; __syncthreads(); }
        float sm = s_red[0]; __syncthreads();
        if (tid < Sz)
            out_probs[(size_t)b * Sz + tid] = e / sm;
        float pv = -INFINITY;
        if (tid < Sz) {
            unsigned key0, key1;
#if PARTITIONABLE
            tf2x32(0u, 1u, 0u, (unsigned)t, key0, key1);
#else
            {
                unsigned a0, b0;
                unsigned idx0 = 2u * t, idx1 = 2u * t + 1u;
                if (idx0 < Sz) { tf2x32(0u, 1u, idx0, idx0 + Sz, a0, b0); key0 = a0; }
                else           { tf2x32(0u, 1u, idx0 - Sz, idx0, a0, b0); key0 = b0; }
                if (idx1 < Sz) { tf2x32(0u, 1u, idx1, idx1 + Sz, a0, b0); key1 = a0; }
                else           { tf2x32(0u, 1u, idx1 - Sz, idx1, a0, b0); key1 = b0; }
            }
#endif
            unsigned m0 = (unsigned)(b * Sz + tid);
            unsigned ra, rb, bits;
#if PARTITIONABLE
            tf2x32(key0, key1, 0u, m0, ra, rb);
            bits = ra ^ rb;
#else
            const unsigned half = (Bz * Sz) / 2;
            if (m0 < half) { tf2x32(key0, key1, m0, m0 + half, ra, rb); bits = ra; }
            else           { tf2x32(key0, key1, m0 - half, m0, ra, rb); bits = rb; }
#endif
            float f = __uint_as_float((bits >> 9) | 0x3f800000u) - 1.0f;
            float u = fmaxf(f, 1.17549435e-38f);
            pv = v - logf(-logf(u));
        }
        s_red[tid] = pv; s_ridx[tid] = tid; __syncthreads();
#pragma unroll
        for (int o = 256; o; o >>= 1) {
            if (tid < o) {
                float a2 = s_red[tid], c2 = s_red[tid + o];
                int ia = s_ridx[tid], ic = s_ridx[tid + o];
                if (c2 > a2 || (c2 == a2 && ic < ia)) { s_red[tid] = c2; s_ridx[tid] = ic; }
            }
            __syncthreads();
        }
        if (!tid) {
            int id = s_ridx[0];
            g_idx[b] = id;
            out_idx[b] = (float)id;
        }
    }
}

// ---------------- host ----------------
template <typename T>
static T* symaddr(const void* sym) {
    void* p = nullptr;
    cudaGetSymbolAddress(&p, sym);
    return (T*)p;
}

extern "C" void kernel_launch(void* const* d_in, const int* in_sizes, int n_in,
                              void* d_out, int out_size) {
    const float* in_inputs = (const float*)d_in[0];
    const float* in_emb    = (const float*)d_in[1];
    const float* in_eWih   = (const float*)d_in[2];
    const float* in_eWhh   = (const float*)d_in[3];
    const float* in_ebih   = (const float*)d_in[4];
    const float* in_ebhh   = (const float*)d_in[5];
    const float* in_dWih   = (const float*)d_in[6];
    const float* in_dWhh   = (const float*)d_in[7];
    const float* in_dbih   = (const float*)d_in[8];
    const float* in_dbhh   = (const float*)d_in[9];
    const float* in_gWq    = (const float*)d_in[10];
    const float* in_gbq    = (const float*)d_in[11];
    const float* in_gWr    = (const float*)d_in[12];
    const float* in_gbr    = (const float*)d_in[13];
    const float* in_gV     = (const float*)d_in[14];
    const float* in_pWq    = (const float*)d_in[15];
    const float* in_pbq    = (const float*)d_in[16];
    const float* in_pWr    = (const float*)d_in[17];
    const float* in_pbr    = (const float*)d_in[18];
    const float* in_pV     = (const float*)d_in[19];
    const float* in_start  = (const float*)d_in[20];
    float* out = (float*)d_out;

    float* p_h0 = symaddr<float>(g_h0);
    float* p_h1 = symaddr<float>(g_h1);

    k_init<<<512, 256>>>();
    k_prep<<<4, 256>>>(in_emb, in_eWih, in_dWih, in_start);

    for (int t = 0; t < Sz; t++) {
        const float* rh = (t & 1) ? p_h1 : p_h0;
        float* wh       = (t & 1) ? p_h0 : p_h1;
        k_lstm_step<<<128, 256>>>(rh, wh, in_eWhh, in_ebih, in_ebhh, in_inputs, t, 0);
    }

    {
        dim3 grid(Hz / 64, (Bz * Sz) / 64, 2);
        k_ref<<<grid, 256>>>(in_gWr, in_gbr, in_pWr, in_pbr);
    }

    float* out_probs = out;
    float* out_idx = out + (size_t)Sz * Bz * Sz;
    for (int t = 0; t < Sz; t++) {
        const float* rh = (t & 1) ? p_h1 : p_h0;
        float* wh       = (t & 1) ? p_h0 : p_h1;
        k_lstm_step<<<128, 256>>>(rh, wh, in_dWhh, in_dbih, in_dbhh, in_inputs, t, 1);
        k_dec_attn<<<Bz, 512>>>(wh, in_gWq, in_gbq, in_gV, in_pWq, in_pbq, in_pV,
                                out_probs + (size_t)t * Bz * Sz,
                                out_idx + (size_t)t * Bz, t);
    }
    (void)in_sizes; (void)n_in; (void)out_size;
}

// round 7
// speedup vs baseline: 1.6246x; 1.6246x over previous
#include <cuda_runtime.h>
#include <cuda_bf16.h>
#include <math.h>
#include <stdint.h>

#define Bz 512
#define Sz 100
#define Ez 256
#define Hz 256
#define G4 1024
#define C_EXPLORE 10.0f
#define PARTITIONABLE 1

// ---------------- device state ----------------
__device__ float g_h0[Bz * Hz];
__device__ float g_h1[Bz * Hz];
__device__ float g_c[Bz * Hz];
__device__ float g_enc[(size_t)Bz * Sz * Hz];
__device__ float g_refg[(size_t)Bz * Sz * Hz];
__device__ float g_refp[(size_t)Bz * Sz * Hz];
__device__ float g_Penc[2 * G4];
__device__ float g_Pdec[2 * G4];
__device__ float g_startproj[G4];
__device__ int g_idx[Bz];
__device__ unsigned char g_mask[Bz * Sz];

__device__ __forceinline__ float sigf(float x) {
    return 0.5f + 0.5f * tanhf(0.5f * x);
}

// ---------------- threefry2x32 ----------------
__device__ __forceinline__ unsigned rotl32(unsigned v, int r) {
    return (v << r) | (v >> (32 - r));
}
__device__ __forceinline__ void tf2x32(unsigned k0, unsigned k1,
                                       unsigned x0, unsigned x1,
                                       unsigned& o0, unsigned& o1) {
    unsigned ks2 = 0x1BD11BDAu ^ k0 ^ k1;
    x0 += k0; x1 += k1;
#define TF_G(a,b,c,d) \
    x0 += x1; x1 = rotl32(x1,a); x1 ^= x0; \
    x0 += x1; x1 = rotl32(x1,b); x1 ^= x0; \
    x0 += x1; x1 = rotl32(x1,c); x1 ^= x0; \
    x0 += x1; x1 = rotl32(x1,d); x1 ^= x0;
    TF_G(13,15,26,6);  x0 += k1;  x1 += ks2 + 1u;
    TF_G(17,29,16,24); x0 += ks2; x1 += k0 + 2u;
    TF_G(13,15,26,6);  x0 += k0;  x1 += k1 + 3u;
    TF_G(17,29,16,24); x0 += k1;  x1 += ks2 + 4u;
    TF_G(13,15,26,6);  x0 += ks2; x1 += k0 + 5u;
#undef TF_G
    o0 = x0; o1 = x1;
}

// ---------------- setup ----------------
__global__ void k_init() {
    int i = blockIdx.x * blockDim.x + threadIdx.x;
    if (i < Bz * Hz) { g_h0[i] = 0.f; g_c[i] = 0.f; }
    if (i < Bz * Sz) g_mask[i] = 0;
    if (i < Bz) g_idx[i] = 0;
}

__global__ void k_prep(const float* __restrict__ emb,
                       const float* __restrict__ eWih,
                       const float* __restrict__ dWih,
                       const float* __restrict__ start) {
    int j = blockIdx.x * 256 + threadIdx.x;
    if (j >= G4) return;
    float pe0 = 0.f, pe1 = 0.f, pd0 = 0.f, pd1 = 0.f, sp = 0.f;
    for (int e = 0; e < Ez; e++) {
        float we = eWih[j * Ez + e], wd = dWih[j * Ez + e];
        pe0 = fmaf(emb[e], we, pe0);
        pe1 = fmaf(emb[Ez + e], we, pe1);
        pd0 = fmaf(emb[e], wd, pd0);
        pd1 = fmaf(emb[Ez + e], wd, pd1);
        sp  = fmaf(start[e], wd, sp);
    }
    g_Penc[j] = pe0; g_Penc[G4 + j] = pe1;
    g_Pdec[j] = pd0; g_Pdec[G4 + j] = pd1;
    g_startproj[j] = sp;
}

// ---------------- fused gates GEMM + LSTM cell, double-buffered ----------------
__global__ void __launch_bounds__(256) k_lstm_step(const float* __restrict__ rh,
                                                   float* __restrict__ wh,
                                                   const float* __restrict__ W,
                                                   const float* __restrict__ bih,
                                                   const float* __restrict__ bhh,
                                                   const float* __restrict__ inp,
                                                   int t, int is_dec) {
    __shared__ float sA[2][32 * 36];
    __shared__ float sW[2][4 * 32 * 33];
    const int tid = threadIdx.x, bid = blockIdx.x;
    const int tx = tid & 31, ty = tid >> 5;
    const int bm = (bid >> 3) * 32, jn = (bid & 7) * 32;
    const int j = jn + tx;
    const int lrow = tid >> 3;
    const int lk = (tid & 7) << 2;

    const float* Ab  = rh + (size_t)(bm + lrow) * Hz + lk;
    const float* Wb0 = W + (size_t)(jn + lrow) * Hz + lk;
    const float* Wb1 = Wb0 + (size_t)256 * Hz;
    const float* Wb2 = Wb0 + (size_t)512 * Hz;
    const float* Wb3 = Wb0 + (size_t)768 * Hz;

    float4 pa  = *(const float4*)Ab;
    float4 pw0 = *(const float4*)Wb0;
    float4 pw1 = *(const float4*)Wb1;
    float4 pw2 = *(const float4*)Wb2;
    float4 pw3 = *(const float4*)Wb3;

    float acc[4][4];
#pragma unroll
    for (int g = 0; g < 4; g++)
#pragma unroll
        for (int r = 0; r < 4; r++) acc[g][r] = 0.f;

    for (int k0 = 0; k0 < Hz; k0 += 32) {
        float* a_s = sA[(k0 >> 5) & 1];
        float* w_s = sW[(k0 >> 5) & 1];
        a_s[(lk + 0) * 36 + lrow] = pa.x;
        a_s[(lk + 1) * 36 + lrow] = pa.y;
        a_s[(lk + 2) * 36 + lrow] = pa.z;
        a_s[(lk + 3) * 36 + lrow] = pa.w;
        {
            float* w0 = w_s;
            w0[(lk + 0) * 33 + lrow] = pw0.x; w0[(lk + 1) * 33 + lrow] = pw0.y;
            w0[(lk + 2) * 33 + lrow] = pw0.z; w0[(lk + 3) * 33 + lrow] = pw0.w;
            float* w1 = w_s + 1056;
            w1[(lk + 0) * 33 + lrow] = pw1.x; w1[(lk + 1) * 33 + lrow] = pw1.y;
            w1[(lk + 2) * 33 + lrow] = pw1.z; w1[(lk + 3) * 33 + lrow] = pw1.w;
            float* w2 = w_s + 2112;
            w2[(lk + 0) * 33 + lrow] = pw2.x; w2[(lk + 1) * 33 + lrow] = pw2.y;
            w2[(lk + 2) * 33 + lrow] = pw2.z; w2[(lk + 3) * 33 + lrow] = pw2.w;
            float* w3 = w_s + 3168;
            w3[(lk + 0) * 33 + lrow] = pw3.x; w3[(lk + 1) * 33 + lrow] = pw3.y;
            w3[(lk + 2) * 33 + lrow] = pw3.z; w3[(lk + 3) * 33 + lrow] = pw3.w;
        }
        __syncthreads();
        if (k0 + 32 < Hz) {
            pa  = *(const float4*)(Ab + k0 + 32);
            pw0 = *(const float4*)(Wb0 + k0 + 32);
            pw1 = *(const float4*)(Wb1 + k0 + 32);
            pw2 = *(const float4*)(Wb2 + k0 + 32);
            pw3 = *(const float4*)(Wb3 + k0 + 32);
        }
#pragma unroll 8
        for (int k = 0; k < 32; k++) {
            float4 a4 = *(const float4*)&a_s[k * 36 + (ty << 2)];
            float w0 = w_s[k * 33 + tx];
            float w1 = w_s[1056 + k * 33 + tx];
            float w2 = w_s[2112 + k * 33 + tx];
            float w3 = w_s[3168 + k * 33 + tx];
            acc[0][0] = fmaf(a4.x, w0, acc[0][0]); acc[0][1] = fmaf(a4.y, w0, acc[0][1]);
            acc[0][2] = fmaf(a4.z, w0, acc[0][2]); acc[0][3] = fmaf(a4.w, w0, acc[0][3]);
            acc[1][0] = fmaf(a4.x, w1, acc[1][0]); acc[1][1] = fmaf(a4.y, w1, acc[1][1]);
            acc[1][2] = fmaf(a4.z, w1, acc[1][2]); acc[1][3] = fmaf(a4.w, w1, acc[1][3]);
            acc[2][0] = fmaf(a4.x, w2, acc[2][0]); acc[2][1] = fmaf(a4.y, w2, acc[2][1]);
            acc[2][2] = fmaf(a4.z, w2, acc[2][2]); acc[2][3] = fmaf(a4.w, w2, acc[2][3]);
            acc[3][0] = fmaf(a4.x, w3, acc[3][0]); acc[3][1] = fmaf(a4.y, w3, acc[3][1]);
            acc[3][2] = fmaf(a4.z, w3, acc[3][2]); acc[3][3] = fmaf(a4.w, w3, acc[3][3]);
        }
    }

    const float* P = is_dec ? g_Pdec : g_Penc;
    float xb[4], pb0[4], pb1[4];
#pragma unroll
    for (int g = 0; g < 4; g++) {
        pb0[g] = P[(g << 8) + j];
        pb1[g] = P[G4 + (g << 8) + j];
        xb[g]  = bih[(g << 8) + j] + bhh[(g << 8) + j];
    }
#pragma unroll
    for (int r = 0; r < 4; r++) {
        int b = bm + (ty << 2) + r;
        float xg[4];
        if (is_dec && t == 0) {
#pragma unroll
            for (int g = 0; g < 4; g++) xg[g] = g_startproj[(g << 8) + j];
        } else {
            int s = is_dec ? g_idx[b] : t;
            float c0 = inp[(b * 2) * Sz + s];
            float c1 = inp[(b * 2 + 1) * Sz + s];
#pragma unroll
            for (int g = 0; g < 4; g++) xg[g] = fmaf(c0, pb0[g], c1 * pb1[g]);
        }
        float gi = acc[0][r] + xg[0] + xb[0];
        float gf = acc[1][r] + xg[1] + xb[1];
        float gc = acc[2][r] + xg[2] + xb[2];
        float go = acc[3][r] + xg[3] + xb[3];
        float cc = sigf(gf) * g_c[b * Hz + j] + sigf(gi) * tanhf(gc);
        g_c[b * Hz + j] = cc;
        float hh = sigf(go) * tanhf(cc);
        wh[b * Hz + j] = hh;
        if (!is_dec) g_enc[(size_t)(b * Sz + t) * Hz + j] = hh;
    }
}

// ---------------- ref projections (z=0: glimpse, z=1: pointer) ----------------
__global__ void __launch_bounds__(256) k_ref(const float* __restrict__ gWr,
                                             const float* __restrict__ gbr,
                                             const float* __restrict__ pWr,
                                             const float* __restrict__ pbr) {
    __shared__ float As[16][64];
    __shared__ float Ws[16][64];
    const float* A = g_enc;
    const float* W = blockIdx.z ? pWr : gWr;
    const float* bias = blockIdx.z ? pbr : gbr;
    float* C = blockIdx.z ? g_refp : g_refg;
    const int K = Hz, N = Hz;
    const int bm = blockIdx.y * 64;
    const int bn = blockIdx.x * 64;
    const int t = threadIdx.x;
    const int tx = t & 15, ty = t >> 4;
    const int lr = t >> 2, lc = (t & 3) << 2;
    float acc[4][4];
#pragma unroll
    for (int i = 0; i < 4; i++)
#pragma unroll
        for (int jj = 0; jj < 4; jj++) acc[i][jj] = 0.f;
    const float* Ab = A + (size_t)(bm + lr) * K + lc;
    const float* Wb = W + (size_t)(bn + lr) * K + lc;
    for (int k0 = 0; k0 < K; k0 += 16) {
        float4 av = *(const float4*)(Ab + k0);
        float4 wv = *(const float4*)(Wb + k0);
        As[lc + 0][lr] = av.x; As[lc + 1][lr] = av.y;
        As[lc + 2][lr] = av.z; As[lc + 3][lr] = av.w;
        Ws[lc + 0][lr] = wv.x; Ws[lc + 1][lr] = wv.y;
        Ws[lc + 2][lr] = wv.z; Ws[lc + 3][lr] = wv.w;
        __syncthreads();
#pragma unroll
        for (int k = 0; k < 16; k++) {
            float4 a4 = *(const float4*)&As[k][ty << 2];
            float4 w4 = *(const float4*)&Ws[k][tx << 2];
            float am[4] = {a4.x, a4.y, a4.z, a4.w};
            float wn[4] = {w4.x, w4.y, w4.z, w4.w};
#pragma unroll
            for (int i = 0; i < 4; i++)
#pragma unroll
                for (int jj = 0; jj < 4; jj++)
                    acc[i][jj] = fmaf(am[i], wn[jj], acc[i][jj]);
        }
        __syncthreads();
    }
#pragma unroll
    for (int i = 0; i < 4; i++) {
        int m = bm + (ty << 2) + i;
#pragma unroll
        for (int jj = 0; jj < 4; jj++) {
            int n = bn + (tx << 2) + jj;
            C[(size_t)m * N + n] = acc[i][jj] + bias[n];
        }
    }
}

// ---------------- fused decoder attention + sample: TWO b per block, 512 thr ----------------
__global__ void __launch_bounds__(512) k_dec_attn(const float* __restrict__ h,
                                                  const float* __restrict__ gWq,
                                                  const float* __restrict__ gbq,
                                                  const float* __restrict__ gV,
                                                  const float* __restrict__ pWq,
                                                  const float* __restrict__ pbq,
                                                  const float* __restrict__ pV,
                                                  float* __restrict__ out_probs,
                                                  float* __restrict__ out_idx,
                                                  int t) {
    __shared__ __align__(16) float s_h[2][Hz];
    __shared__ __align__(16) float s_qq[2][Hz];
    __shared__ __align__(16) float s_q[2][Hz];
    __shared__ __align__(16) float s_Vg[Hz];
    __shared__ __align__(16) float s_Vp[Hz];
    __shared__ float s_lg[2][128];
    __shared__ float s_w[2][128];
    __shared__ float s_red[2][256];
    __shared__ int s_ridx[2][256];
    __shared__ unsigned char s_m[2][104];

    const int tid = threadIdx.x;
    const int half = tid >> 8;          // 0/1
    const int ht = tid & 255;
    const int b = (blockIdx.x << 1) + half;
    const int wd = tid >> 5;            // 0..15
    const int hf = wd >> 3;             // warp's half
    const int wl = wd & 7;              // warp index within half
    const int ln = tid & 31;
    const int bw = (blockIdx.x << 1) + hf;  // b for warp-level loops

    if (t > 0 && ht == 0) g_mask[b * Sz + g_idx[b]] = 1;
    __syncthreads();
    if (ht < Sz) s_m[half][ht] = g_mask[b * Sz + ht];
    s_h[half][ht] = h[b * Hz + ht];
    if (tid < Hz) s_Vg[tid] = gV[tid];
    else if (tid < 2 * Hz) s_Vp[tid - Hz] = pV[tid - Hz];
    __syncthreads();

    // qq = h @ gWq^T + gbq for BOTH b's, reading W once
    if (tid < Hz) {
        float a0 = 0.f, a1 = 0.f;
        const float* wr = gWq + (size_t)tid * Hz;
#pragma unroll 8
        for (int k0 = 0; k0 < Hz; k0 += 4) {
            float4 wv = *(const float4*)&wr[k0];
            float4 h0 = *(const float4*)&s_h[0][k0];
            float4 h1 = *(const float4*)&s_h[1][k0];
            a0 = fmaf(h0.x, wv.x, a0); a1 = fmaf(h1.x, wv.x, a1);
            a0 = fmaf(h0.y, wv.y, a0); a1 = fmaf(h1.y, wv.y, a1);
            a0 = fmaf(h0.z, wv.z, a0); a1 = fmaf(h1.z, wv.z, a1);
            a0 = fmaf(h0.w, wv.w, a0); a1 = fmaf(h1.w, wv.w, a1);
        }
        float bq = gbq[tid];
        s_qq[0][tid] = a0 + bq;
        s_qq[1][tid] = a1 + bq;
    }
    __syncthreads();
    // glimpse logits: 8 warps per half over s
    for (int s = wl; s < Sz; s += 8) {
        float a0 = 0.f, a1 = 0.f;
        if (!s_m[hf][s]) {
            const float4* rg4 = (const float4*)(g_refg + ((size_t)bw * Sz + s) * Hz);
#pragma unroll
            for (int i = 0; i < 2; i++) {
                int c = i * 32 + ln;
                float4 rv = rg4[c];
                float4 qv = *(const float4*)&s_qq[hf][c << 2];
                float4 vv = *(const float4*)&s_Vg[c << 2];
                a0 = fmaf(vv.x, tanhf(qv.x + rv.x), a0);
                a1 = fmaf(vv.y, tanhf(qv.y + rv.y), a1);
                a0 = fmaf(vv.z, tanhf(qv.z + rv.z), a0);
                a1 = fmaf(vv.w, tanhf(qv.w + rv.w), a1);
            }
        }
        float a = a0 + a1;
#pragma unroll
        for (int o = 16; o; o >>= 1) a += __shfl_xor_sync(0xffffffffu, a, o);
        if (!ln) s_lg[hf][s] = s_m[hf][s] ? -INFINITY : a;
    }
    __syncthreads();
    // softmax -> s_w (per half, 256 threads each)
    {
        float v = (ht < Sz) ? s_lg[half][ht] : -INFINITY;
        s_red[half][ht] = v; __syncthreads();
#pragma unroll
        for (int o = 128; o; o >>= 1) { if (ht < o) s_red[half][ht] = fmaxf(s_red[half][ht], s_red[half][ht + o]); __syncthreads(); }
        float m = s_red[half][0]; __syncthreads();
        float e = (ht < Sz) ? expf(v - m) : 0.f;
        s_red[half][ht] = e; __syncthreads();
#pragma unroll
        for (int o = 128; o; o >>= 1) { if (ht < o) s_red[half][ht] += s_red[half][ht + o]; __syncthreads(); }
        float sm = s_red[half][0]; __syncthreads();
        if (ht < 128) s_w[half][ht] = (ht < Sz) ? e / sm : 0.f;
    }
    __syncthreads();
    // q = sum_s w[s] * enc[b,s,:]  (each half handles its own b; coalesced over ht)
    {
        float a0 = 0.f, a1 = 0.f;
        const float* eb = g_enc + (size_t)b * Sz * Hz + ht;
        for (int s = 0; s < Sz; s += 2) {
            a0 = fmaf(s_w[half][s], eb[(size_t)s * Hz], a0);
            a1 = fmaf(s_w[half][s + 1], eb[(size_t)(s + 1) * Hz], a1);
        }
        s_q[half][ht] = a0 + a1;
    }
    __syncthreads();
    // qq2 = q @ pWq^T + pbq for both b's
    if (tid < Hz) {
        float a0 = 0.f, a1 = 0.f;
        const float* wr = pWq + (size_t)tid * Hz;
#pragma unroll 8
        for (int k0 = 0; k0 < Hz; k0 += 4) {
            float4 wv = *(const float4*)&wr[k0];
            float4 q0 = *(const float4*)&s_q[0][k0];
            float4 q1 = *(const float4*)&s_q[1][k0];
            a0 = fmaf(q0.x, wv.x, a0); a1 = fmaf(q1.x, wv.x, a1);
            a0 = fmaf(q0.y, wv.y, a0); a1 = fmaf(q1.y, wv.y, a1);
            a0 = fmaf(q0.z, wv.z, a0); a1 = fmaf(q1.z, wv.z, a1);
            a0 = fmaf(q0.w, wv.w, a0); a1 = fmaf(q1.w, wv.w, a1);
        }
        float bq = pbq[tid];
        s_qq[0][tid] = a0 + bq;
        s_qq[1][tid] = a1 + bq;
    }
    __syncthreads();
    // pointer logits
    for (int s = wl; s < Sz; s += 8) {
        float a0 = 0.f, a1 = 0.f;
        if (!s_m[hf][s]) {
            const float4* rp4 = (const float4*)(g_refp + ((size_t)bw * Sz + s) * Hz);
#pragma unroll
            for (int i = 0; i < 2; i++) {
                int c = i * 32 + ln;
                float4 rv = rp4[c];
                float4 qv = *(const float4*)&s_qq[hf][c << 2];
                float4 vv = *(const float4*)&s_Vp[c << 2];
                a0 = fmaf(vv.x, tanhf(qv.x + rv.x), a0);
                a1 = fmaf(vv.y, tanhf(qv.y + rv.y), a1);
                a0 = fmaf(vv.z, tanhf(qv.z + rv.z), a0);
                a1 = fmaf(vv.w, tanhf(qv.w + rv.w), a1);
            }
        }
        float a = a0 + a1;
#pragma unroll
        for (int o = 16; o; o >>= 1) a += __shfl_xor_sync(0xffffffffu, a, o);
        if (!ln) s_lg[hf][s] = s_m[hf][s] ? -INFINITY : C_EXPLORE * tanhf(a);
    }
    __syncthreads();
    // softmax -> probs; gumbel argmax -> idx (per half)
    {
        float v = (ht < Sz) ? s_lg[half][ht] : -INFINITY;
        s_red[half][ht] = v; __syncthreads();
#pragma unroll
        for (int o = 128; o; o >>= 1) { if (ht < o) s_red[half][ht] = fmaxf(s_red[half][ht], s_red[half][ht + o]); __syncthreads(); }
        float m = s_red[half][0]; __syncthreads();
        float e = (ht < Sz) ? expf(v - m) : 0.f;
        s_red[half][ht] = e; __syncthreads();
#pragma unroll
        for (int o = 128; o; o >>= 1) { if (ht < o) s_red[half][ht] += s_red[half][ht + o]; __syncthreads(); }
        float sm = s_red[half][0]; __syncthreads();
        if (ht < Sz)
            out_probs[(size_t)b * Sz + ht] = e / sm;
        float pv = -INFINITY;
        if (ht < Sz) {
            unsigned key0, key1;
#if PARTITIONABLE
            tf2x32(0u, 1u, 0u, (unsigned)t, key0, key1);
#else
            {
                unsigned a0, b0;
                unsigned idx0 = 2u * t, idx1 = 2u * t + 1u;
                if (idx0 < Sz) { tf2x32(0u, 1u, idx0, idx0 + Sz, a0, b0); key0 = a0; }
                else           { tf2x32(0u, 1u, idx0 - Sz, idx0, a0, b0); key0 = b0; }
                if (idx1 < Sz) { tf2x32(0u, 1u, idx1, idx1 + Sz, a0, b0); key1 = a0; }
                else           { tf2x32(0u, 1u, idx1 - Sz, idx1, a0, b0); key1 = b0; }
            }
#endif
            unsigned m0 = (unsigned)(b * Sz + ht);
            unsigned ra, rb, bits;
#if PARTITIONABLE
            tf2x32(key0, key1, 0u, m0, ra, rb);
            bits = ra ^ rb;
#else
            const unsigned halfn = (Bz * Sz) / 2;
            if (m0 < halfn) { tf2x32(key0, key1, m0, m0 + halfn, ra, rb); bits = ra; }
            else            { tf2x32(key0, key1, m0 - halfn, m0, ra, rb); bits = rb; }
#endif
            float f = __uint_as_float((bits >> 9) | 0x3f800000u) - 1.0f;
            float u = fmaxf(f, 1.17549435e-38f);
            pv = v - logf(-logf(u));
        }
        s_red[half][ht] = pv; s_ridx[half][ht] = ht; __syncthreads();
#pragma unroll
        for (int o = 128; o; o >>= 1) {
            if (ht < o) {
                float a2 = s_red[half][ht], c2 = s_red[half][ht + o];
                int ia = s_ridx[half][ht], ic = s_ridx[half][ht + o];
                if (c2 > a2 || (c2 == a2 && ic < ia)) { s_red[half][ht] = c2; s_ridx[half][ht] = ic; }
            }
            __syncthreads();
        }
        if (!ht) {
            int id = s_ridx[half][0];
            g_idx[b] = id;
            out_idx[b] = (float)id;
        }
    }
}

// ---------------- host ----------------
template <typename T>
static T* symaddr(const void* sym) {
    void* p = nullptr;
    cudaGetSymbolAddress(&p, sym);
    return (T*)p;
}

extern "C" void kernel_launch(void* const* d_in, const int* in_sizes, int n_in,
                              void* d_out, int out_size) {
    const float* in_inputs = (const float*)d_in[0];
    const float* in_emb    = (const float*)d_in[1];
    const float* in_eWih   = (const float*)d_in[2];
    const float* in_eWhh   = (const float*)d_in[3];
    const float* in_ebih   = (const float*)d_in[4];
    const float* in_ebhh   = (const float*)d_in[5];
    const float* in_dWih   = (const float*)d_in[6];
    const float* in_dWhh   = (const float*)d_in[7];
    const float* in_dbih   = (const float*)d_in[8];
    const float* in_dbhh   = (const float*)d_in[9];
    const float* in_gWq    = (const float*)d_in[10];
    const float* in_gbq    = (const float*)d_in[11];
    const float* in_gWr    = (const float*)d_in[12];
    const float* in_gbr    = (const float*)d_in[13];
    const float* in_gV     = (const float*)d_in[14];
    const float* in_pWq    = (const float*)d_in[15];
    const float* in_pbq    = (const float*)d_in[16];
    const float* in_pWr    = (const float*)d_in[17];
    const float* in_pbr    = (const float*)d_in[18];
    const float* in_pV     = (const float*)d_in[19];
    const float* in_start  = (const float*)d_in[20];
    float* out = (float*)d_out;

    float* p_h0 = symaddr<float>(g_h0);
    float* p_h1 = symaddr<float>(g_h1);

    k_init<<<512, 256>>>();
    k_prep<<<4, 256>>>(in_emb, in_eWih, in_dWih, in_start);

    for (int t = 0; t < Sz; t++) {
        const float* rh = (t & 1) ? p_h1 : p_h0;
        float* wh       = (t & 1) ? p_h0 : p_h1;
        k_lstm_step<<<128, 256>>>(rh, wh, in_eWhh, in_ebih, in_ebhh, in_inputs, t, 0);
    }

    {
        dim3 grid(Hz / 64, (Bz * Sz) / 64, 2);
        k_ref<<<grid, 256>>>(in_gWr, in_gbr, in_pWr, in_pbr);
    }

    float* out_probs = out;
    float* out_idx = out + (size_t)Sz * Bz * Sz;
    for (int t = 0; t < Sz; t++) {
        const float* rh = (t & 1) ? p_h1 : p_h0;
        float* wh       = (t & 1) ? p_h0 : p_h1;
        k_lstm_step<<<128, 256>>>(rh, wh, in_dWhh, in_dbih, in_dbhh, in_inputs, t, 1);
        k_dec_attn<<<Bz / 2, 512>>>(wh, in_gWq, in_gbq, in_gV, in_pWq, in_pbq, in_pV,
                                    out_probs + (size_t)t * Bz * Sz,
                                    out_idx + (size_t)t * Bz, t);
    }
    (void)in_sizes; (void)n_in; (void)out_size;
}